// round 2
// baseline (speedup 1.0000x reference)
#include <cuda_runtime.h>

#define DIMC   512
#define BC     512
#define KC     128
#define NWARP  8
#define TPB    256
#define TAILS_PER_WARP (KC / NWARP)
#define EPSF   1e-6f
#define MARGINF 2.0f

__device__ __forceinline__ float softplusf(float x) {
    return (x > 20.f) ? x : log1pf(expf(x));
}

__global__ __launch_bounds__(TPB, 3)
void ultrae_kernel(const float* __restrict__ emb,
                   const float* __restrict__ rel_boost,
                   const float* __restrict__ rot_left,
                   const float* __restrict__ rot_right,
                   const float* __restrict__ bias_head,
                   const float* __restrict__ bias_tail,
                   const int*   __restrict__ u_idx,
                   const int*   __restrict__ r_idx,
                   const int*   __restrict__ v_idx,
                   float*       __restrict__ out)
{
    __shared__ __align__(16) float sh[DIMC];
    __shared__ float red[NWARP];
    __shared__ float a_sh;
    __shared__ float s_sq[KC];
    __shared__ float s_dt[KC];
    __shared__ float s_t1[KC];

    const int b    = blockIdx.x;
    const int tid  = threadIdx.x;          // pair index 0..255
    const int lane = tid & 31;
    const int warp = tid >> 5;
    const int u    = u_idx[b];
    const int r    = r_idx[b];

    // ---------------- head preprocessing (per block) ----------------
    const float* hrow = emb + (size_t)u * DIMC;
    float x0 = hrow[2 * tid];
    float x1 = hrow[2 * tid + 1];
    if (tid == 0) x0 = 0.f;                               // proj_tan0
    float acc = (tid == 0) ? (-x1 * x1) : (x0 * x0 + x1 * x1);
    #pragma unroll
    for (int o = 16; o; o >>= 1) acc += __shfl_xor_sync(0xffffffffu, acc, o);
    if (lane == 0) red[warp] = acc;
    __syncthreads();
    if (tid == 0) {
        float a = 0.f;
        #pragma unroll
        for (int w = 0; w < NWARP; ++w) a += red[w];
        a_sh = a;
    }
    __syncthreads();
    const float a = a_sh;

    float c, s;
    if (a > 0.f) {
        float sp = sqrtf(fmaxf(a, EPSF));
        c = coshf(sp);  s = sinhf(sp) / sp;
    } else {
        float st = sqrtf(fmaxf(-a, EPSF));
        c = cosf(st);   s = sinf(st) / st;
    }
    float y0 = (tid == 0) ? c : s * x0;
    float y1 = s * x1;

    // givens_rotations with rot_right
    {
        float g0 = rot_right[(size_t)r * DIMC + 2 * tid];
        float g1 = rot_right[(size_t)r * DIMC + 2 * tid + 1];
        float n  = fmaxf(sqrtf(g0 * g0 + g1 * g1), 1e-15f);
        float cr = g0 / n, sr = g1 / n;
        sh[2 * tid]     = cr * y0 - sr * y1;
        sh[2 * tid + 1] = cr * y1 + sr * y0;
    }
    __syncthreads();

    // Lorentz boost: identity except entries mixing (0,510) and (1,511)
    if (tid == 0) {
        float b0 = softplusf(rel_boost[2 * r]);
        float b1 = softplusf(rel_boost[2 * r + 1]);
        float C0 = sqrtf(1.f + b0 * b0);
        float C1 = sqrtf(1.f + b1 * b1);
        float t0 = sh[0], t1 = sh[1];
        float q0 = sh[DIMC - 2], q1 = sh[DIMC - 1];
        sh[0]        = C0 * t0 - b0 * q0;
        sh[DIMC - 2] = C0 * q0 - b0 * t0;
        sh[1]        = C1 * t1 - b1 * q1;
        sh[DIMC - 1] = C1 * q1 - b1 * t1;
    }
    __syncthreads();

    // givens_reflection with rot_left (each thread owns its pair: no hazard)
    {
        float w0 = sh[2 * tid], w1 = sh[2 * tid + 1];
        float l0 = rot_left[(size_t)r * DIMC + 2 * tid];
        float l1 = rot_left[(size_t)r * DIMC + 2 * tid + 1];
        float n  = fmaxf(sqrtf(l0 * l0 + l1 * l1), 1e-15f);
        float cl = l0 / n, sl = l1 / n;
        sh[2 * tid]     = cl * w0 + sl * w1;
        sh[2 * tid + 1] = sl * w0 - cl * w1;
    }
    __syncthreads();

    // each lane keeps its 16 head dims in registers
    const float4 H0 = *(const float4*)&sh[lane * 16 + 0];
    const float4 H1 = *(const float4*)&sh[lane * 16 + 4];
    const float4 H2 = *(const float4*)&sh[lane * 16 + 8];
    const float4 H3 = *(const float4*)&sh[lane * 16 + 12];

    // ------------- tail loop: each warp handles 16 tails, pipelined -------------
    const int kbase = warp * TAILS_PER_WARP;

    // prologue: issue loads for tail 0
    int vi = v_idx[b * KC + kbase];
    const float4* tp = (const float4*)(emb + (size_t)vi * DIMC) + lane * 4;
    float4 T0 = tp[0], T1 = tp[1], T2 = tp[2], T3 = tp[3];

    #pragma unroll
    for (int t = 0; t < TAILS_PER_WARP; ++t) {
        // prefetch next tail while we reduce this one
        float4 N0, N1, N2, N3;
        if (t + 1 < TAILS_PER_WARP) {
            int vin = v_idx[b * KC + kbase + t + 1];
            const float4* np = (const float4*)(emb + (size_t)vin * DIMC) + lane * 4;
            N0 = np[0]; N1 = np[1]; N2 = np[2]; N3 = np[3];
        }

        float sq = T0.x*T0.x + T0.y*T0.y + T0.z*T0.z + T0.w*T0.w
                 + T1.x*T1.x + T1.y*T1.y + T1.z*T1.z + T1.w*T1.w
                 + T2.x*T2.x + T2.y*T2.y + T2.z*T2.z + T2.w*T2.w
                 + T3.x*T3.x + T3.y*T3.y + T3.z*T3.z + T3.w*T3.w;
        float dt = H0.x*T0.x + H0.y*T0.y + H0.z*T0.z + H0.w*T0.w
                 + H1.x*T1.x + H1.y*T1.y + H1.z*T1.z + H1.w*T1.w
                 + H2.x*T2.x + H2.y*T2.y + H2.z*T2.z + H2.w*T2.w
                 + H3.x*T3.x + H3.y*T3.y + H3.z*T3.z + H3.w*T3.w;
        float t1raw = T0.y;   // tail element 1 (raw), valid on lane 0
        if (lane == 0) {
            // a_tail = -u1^2 + sum_{j>=2} u_j^2 ; dot only over spatial dims
            sq -= T0.x * T0.x + 2.f * T0.y * T0.y;
            dt -= H0.x * T0.x + H0.y * T0.y;
        }
        #pragma unroll
        for (int o = 16; o; o >>= 1) {
            sq += __shfl_xor_sync(0xffffffffu, sq, o);
            dt += __shfl_xor_sync(0xffffffffu, dt, o);
        }
        if (lane == 0) {
            s_sq[kbase + t] = sq;
            s_dt[kbase + t] = dt;
            s_t1[kbase + t] = t1raw;
        }

        T0 = N0; T1 = N1; T2 = N2; T3 = N3;
    }
    __syncthreads();

    // ------------- parallel epilogue: threads 0..127 each handle one tail -------------
    if (tid < KC) {
        const float h0 = sh[0];
        const float h1 = sh[1];
        const float nh = sqrtf(h0 * h0 + h1 * h1);

        float sq    = s_sq[tid];
        float dtv   = s_dt[tid];
        float t1raw = s_t1[tid];

        float ct, stf;
        if (sq > 0.f) {
            float sp = sqrtf(fmaxf(sq, EPSF));
            ct = coshf(sp);  stf = sinhf(sp) / sp;
        } else {
            float st = sqrtf(fmaxf(-sq, EPSF));
            ct = cosf(st);   stf = sinf(st) / st;
        }
        float ty0 = ct;              // tail time comp 0 (u0=0 -> c)
        float ty1 = stf * t1raw;     // tail time comp 1
        float nt  = sqrtf(ty0 * ty0 + ty1 * ty1);
        float dxy = stf * dtv;       // dot(xs, ys) = s_t * sum h_j u_j

        float cosang = (h0 * ty0 + h1 * ty1) / (nh * nt);
        cosang = fminf(fmaxf(cosang, -1.f + EPSF), 1.f - EPSF);
        float theta = acosf(cosang);

        float inner = nh * nt - dxy;
        float dh = acoshf(fmaxf(inner, 1.f + EPSF));

        float d1 = nh * theta + dh;
        float d2 = nt * theta + dh;
        float dist = fminf(d1 * d1, d2 * d2);

        int vtail = v_idx[b * KC + tid];
        out[b * KC + tid] = MARGINF - dist + bias_head[u] + bias_tail[vtail];
    }
}

extern "C" void kernel_launch(void* const* d_in, const int* in_sizes, int n_in,
                              void* d_out, int out_size)
{
    const float* emb       = (const float*)d_in[0];
    const float* rel_boost = (const float*)d_in[1];
    const float* rot_left  = (const float*)d_in[2];
    const float* rot_right = (const float*)d_in[3];
    const float* bias_head = (const float*)d_in[4];
    const float* bias_tail = (const float*)d_in[5];
    const int*   u_idx     = (const int*)d_in[6];
    const int*   r_idx     = (const int*)d_in[7];
    const int*   v_idx     = (const int*)d_in[8];

    ultrae_kernel<<<BC, TPB>>>(emb, rel_boost, rot_left, rot_right,
                               bias_head, bias_tail, u_idx, r_idx, v_idx,
                               (float*)d_out);
}

// round 3
// speedup vs baseline: 1.1702x; 1.1702x over previous
#include <cuda_runtime.h>

#define DIMC   512
#define BC     512
#define KC     128
#define YSPLIT 4
#define KBLK   (KC / YSPLIT)          // 32 tails per block
#define NWARP  8
#define TPB    256
#define TAILS_PER_WARP (KBLK / NWARP) // 4
#define EPSF   1e-6f
#define MARGINF 2.0f

__device__ __forceinline__ float softplusf(float x) {
    return (x > 20.f) ? x : log1pf(expf(x));
}

__global__ __launch_bounds__(TPB)
void ultrae_kernel(const float* __restrict__ emb,
                   const float* __restrict__ rel_boost,
                   const float* __restrict__ rot_left,
                   const float* __restrict__ rot_right,
                   const float* __restrict__ bias_head,
                   const float* __restrict__ bias_tail,
                   const int*   __restrict__ u_idx,
                   const int*   __restrict__ r_idx,
                   const int*   __restrict__ v_idx,
                   float*       __restrict__ out)
{
    __shared__ __align__(16) float sh[DIMC];
    __shared__ float red[NWARP];
    __shared__ float a_sh;
    __shared__ float s_sq[KBLK];
    __shared__ float s_dt[KBLK];
    __shared__ float s_t1[KBLK];

    const int b    = blockIdx.x;
    const int yblk = blockIdx.y;
    const int tid  = threadIdx.x;          // pair index 0..255
    const int lane = tid & 31;
    const int warp = tid >> 5;
    const int u    = u_idx[b];
    const int r    = r_idx[b];

    // ---------------- head preprocessing (per block) ----------------
    const float* hrow = emb + (size_t)u * DIMC;
    float x0 = hrow[2 * tid];
    float x1 = hrow[2 * tid + 1];
    if (tid == 0) x0 = 0.f;                               // proj_tan0
    float acc = (tid == 0) ? (-x1 * x1) : (x0 * x0 + x1 * x1);
    #pragma unroll
    for (int o = 16; o; o >>= 1) acc += __shfl_xor_sync(0xffffffffu, acc, o);
    if (lane == 0) red[warp] = acc;
    __syncthreads();
    if (tid == 0) {
        float a = 0.f;
        #pragma unroll
        for (int w = 0; w < NWARP; ++w) a += red[w];
        a_sh = a;
    }
    __syncthreads();
    const float a = a_sh;

    float c, s;
    if (a > 0.f) {
        float sp = sqrtf(fmaxf(a, EPSF));
        c = coshf(sp);  s = sinhf(sp) / sp;
    } else {
        float st = sqrtf(fmaxf(-a, EPSF));
        c = cosf(st);   s = sinf(st) / st;
    }
    float y0 = (tid == 0) ? c : s * x0;
    float y1 = s * x1;

    // givens_rotations with rot_right
    {
        float g0 = rot_right[(size_t)r * DIMC + 2 * tid];
        float g1 = rot_right[(size_t)r * DIMC + 2 * tid + 1];
        float n  = fmaxf(sqrtf(g0 * g0 + g1 * g1), 1e-15f);
        float cr = g0 / n, sr = g1 / n;
        sh[2 * tid]     = cr * y0 - sr * y1;
        sh[2 * tid + 1] = cr * y1 + sr * y0;
    }
    __syncthreads();

    // Lorentz boost: identity except entries mixing (0,510) and (1,511)
    if (tid == 0) {
        float b0 = softplusf(rel_boost[2 * r]);
        float b1 = softplusf(rel_boost[2 * r + 1]);
        float C0 = sqrtf(1.f + b0 * b0);
        float C1 = sqrtf(1.f + b1 * b1);
        float t0 = sh[0], t1 = sh[1];
        float q0 = sh[DIMC - 2], q1 = sh[DIMC - 1];
        sh[0]        = C0 * t0 - b0 * q0;
        sh[DIMC - 2] = C0 * q0 - b0 * t0;
        sh[1]        = C1 * t1 - b1 * q1;
        sh[DIMC - 1] = C1 * q1 - b1 * t1;
    }
    __syncthreads();

    // givens_reflection with rot_left (each thread owns its pair: no hazard)
    {
        float w0 = sh[2 * tid], w1 = sh[2 * tid + 1];
        float l0 = rot_left[(size_t)r * DIMC + 2 * tid];
        float l1 = rot_left[(size_t)r * DIMC + 2 * tid + 1];
        float n  = fmaxf(sqrtf(l0 * l0 + l1 * l1), 1e-15f);
        float cl = l0 / n, sl = l1 / n;
        sh[2 * tid]     = cl * w0 + sl * w1;
        sh[2 * tid + 1] = sl * w0 - cl * w1;
    }
    __syncthreads();

    // each lane keeps its 16 head dims in registers
    const float4 H0 = *(const float4*)&sh[lane * 16 + 0];
    const float4 H1 = *(const float4*)&sh[lane * 16 + 4];
    const float4 H2 = *(const float4*)&sh[lane * 16 + 8];
    const float4 H3 = *(const float4*)&sh[lane * 16 + 12];

    // ------------- tail loop: each warp handles 4 tails of this K-slice -------------
    const int kglob0 = yblk * KBLK;               // first tail of this block
    const int kbase  = warp * TAILS_PER_WARP;     // local within block

    #pragma unroll
    for (int t = 0; t < TAILS_PER_WARP; ++t) {
        const int klocal = kbase + t;
        const int vi = v_idx[b * KC + kglob0 + klocal];
        const float4* tp = (const float4*)(emb + (size_t)vi * DIMC) + lane * 4;
        float4 T0 = tp[0], T1 = tp[1], T2 = tp[2], T3 = tp[3];

        float sq = T0.x*T0.x + T0.y*T0.y + T0.z*T0.z + T0.w*T0.w
                 + T1.x*T1.x + T1.y*T1.y + T1.z*T1.z + T1.w*T1.w
                 + T2.x*T2.x + T2.y*T2.y + T2.z*T2.z + T2.w*T2.w
                 + T3.x*T3.x + T3.y*T3.y + T3.z*T3.z + T3.w*T3.w;
        float dt = H0.x*T0.x + H0.y*T0.y + H0.z*T0.z + H0.w*T0.w
                 + H1.x*T1.x + H1.y*T1.y + H1.z*T1.z + H1.w*T1.w
                 + H2.x*T2.x + H2.y*T2.y + H2.z*T2.z + H2.w*T2.w
                 + H3.x*T3.x + H3.y*T3.y + H3.z*T3.z + H3.w*T3.w;
        float t1raw = T0.y;   // tail element 1 (raw), valid on lane 0
        if (lane == 0) {
            // a_tail = -u1^2 + sum_{j>=2} u_j^2 ; dot only over spatial dims
            sq -= T0.x * T0.x + 2.f * T0.y * T0.y;
            dt -= H0.x * T0.x + H0.y * T0.y;
        }
        #pragma unroll
        for (int o = 16; o; o >>= 1) {
            sq += __shfl_xor_sync(0xffffffffu, sq, o);
            dt += __shfl_xor_sync(0xffffffffu, dt, o);
        }
        if (lane == 0) {
            s_sq[klocal] = sq;
            s_dt[klocal] = dt;
            s_t1[klocal] = t1raw;
        }
    }
    __syncthreads();

    // ------------- parallel epilogue: threads 0..31 each handle one tail -------------
    if (tid < KBLK) {
        const float h0 = sh[0];
        const float h1 = sh[1];
        const float nh = sqrtf(h0 * h0 + h1 * h1);

        float sq    = s_sq[tid];
        float dtv   = s_dt[tid];
        float t1raw = s_t1[tid];

        float ct, stf;
        if (sq > 0.f) {
            float sp = sqrtf(fmaxf(sq, EPSF));
            ct = coshf(sp);  stf = sinhf(sp) / sp;
        } else {
            float st = sqrtf(fmaxf(-sq, EPSF));
            ct = cosf(st);   stf = sinf(st) / st;
        }
        float ty0 = ct;              // tail time comp 0 (u0=0 -> c)
        float ty1 = stf * t1raw;     // tail time comp 1
        float nt  = sqrtf(ty0 * ty0 + ty1 * ty1);
        float dxy = stf * dtv;       // dot(xs, ys) = s_t * sum h_j u_j

        float cosang = (h0 * ty0 + h1 * ty1) / (nh * nt);
        cosang = fminf(fmaxf(cosang, -1.f + EPSF), 1.f - EPSF);
        float theta = acosf(cosang);

        float inner = nh * nt - dxy;
        float dh = acoshf(fmaxf(inner, 1.f + EPSF));

        float d1 = nh * theta + dh;
        float d2 = nt * theta + dh;
        float dist = fminf(d1 * d1, d2 * d2);

        const int kg = kglob0 + tid;
        int vtail = v_idx[b * KC + kg];
        out[b * KC + kg] = MARGINF - dist + bias_head[u] + bias_tail[vtail];
    }
}

extern "C" void kernel_launch(void* const* d_in, const int* in_sizes, int n_in,
                              void* d_out, int out_size)
{
    const float* emb       = (const float*)d_in[0];
    const float* rel_boost = (const float*)d_in[1];
    const float* rot_left  = (const float*)d_in[2];
    const float* rot_right = (const float*)d_in[3];
    const float* bias_head = (const float*)d_in[4];
    const float* bias_tail = (const float*)d_in[5];
    const int*   u_idx     = (const int*)d_in[6];
    const int*   r_idx     = (const int*)d_in[7];
    const int*   v_idx     = (const int*)d_in[8];

    dim3 grid(BC, YSPLIT);
    ultrae_kernel<<<grid, TPB>>>(emb, rel_boost, rot_left, rot_right,
                                 bias_head, bias_tail, u_idx, r_idx, v_idx,
                                 (float*)d_out);
}

// round 4
// speedup vs baseline: 1.3243x; 1.1317x over previous
#include <cuda_runtime.h>

#define DIMC   512
#define BC     512
#define KC     128
#define NWARP  8
#define TPB    256
#define TAILS_PER_WARP (KC / NWARP)   // 16
#define EPSF   1e-6f
#define MARGINF 2.0f

__device__ __forceinline__ float softplusf(float x) {
    return (x > 20.f) ? x : log1pf(expf(x));
}

__global__ __launch_bounds__(TPB)
void ultrae_kernel(const float* __restrict__ emb,
                   const float* __restrict__ rel_boost,
                   const float* __restrict__ rot_left,
                   const float* __restrict__ rot_right,
                   const float* __restrict__ bias_head,
                   const float* __restrict__ bias_tail,
                   const int*   __restrict__ u_idx,
                   const int*   __restrict__ r_idx,
                   const int*   __restrict__ v_idx,
                   float*       __restrict__ out)
{
    __shared__ __align__(16) float sh[DIMC];
    __shared__ float red[NWARP];
    __shared__ float a_sh;
    __shared__ float s_sq[KC];
    __shared__ float s_dt[KC];
    __shared__ float s_t1[KC];

    const int b    = blockIdx.x;
    const int tid  = threadIdx.x;
    const int lane = tid & 31;
    const int warp = tid >> 5;
    const int u    = u_idx[b];
    const int r    = r_idx[b];

    const int kbase = warp * TAILS_PER_WARP;

    // --- issue first tail's gather immediately (independent of head math) ---
    int vi0 = v_idx[b * KC + kbase];
    const float4* tp0 = (const float4*)(emb + (size_t)vi0 * DIMC) + lane * 4;
    float4 A0 = tp0[0], A1 = tp0[1], A2 = tp0[2], A3 = tp0[3];

    // ---------------- head preprocessing (per block) ----------------
    const float* hrow = emb + (size_t)u * DIMC;
    float x0 = hrow[2 * tid];
    float x1 = hrow[2 * tid + 1];
    if (tid == 0) x0 = 0.f;                               // proj_tan0
    float acc = (tid == 0) ? (-x1 * x1) : (x0 * x0 + x1 * x1);
    #pragma unroll
    for (int o = 16; o; o >>= 1) acc += __shfl_xor_sync(0xffffffffu, acc, o);
    if (lane == 0) red[warp] = acc;
    __syncthreads();
    if (tid == 0) {
        float a = 0.f;
        #pragma unroll
        for (int w = 0; w < NWARP; ++w) a += red[w];
        a_sh = a;
    }
    __syncthreads();
    const float a = a_sh;

    float c, s;
    if (a > 0.f) {
        float sp = sqrtf(fmaxf(a, EPSF));
        c = coshf(sp);  s = sinhf(sp) / sp;
    } else {
        float st = sqrtf(fmaxf(-a, EPSF));
        c = cosf(st);   s = sinf(st) / st;
    }
    float y0 = (tid == 0) ? c : s * x0;
    float y1 = s * x1;

    // givens_rotations with rot_right
    {
        float g0 = rot_right[(size_t)r * DIMC + 2 * tid];
        float g1 = rot_right[(size_t)r * DIMC + 2 * tid + 1];
        float n  = fmaxf(sqrtf(g0 * g0 + g1 * g1), 1e-15f);
        float cr = g0 / n, sr = g1 / n;
        sh[2 * tid]     = cr * y0 - sr * y1;
        sh[2 * tid + 1] = cr * y1 + sr * y0;
    }
    __syncthreads();

    // Lorentz boost: identity except entries mixing (0,510) and (1,511)
    if (tid == 0) {
        float b0 = softplusf(rel_boost[2 * r]);
        float b1 = softplusf(rel_boost[2 * r + 1]);
        float C0 = sqrtf(1.f + b0 * b0);
        float C1 = sqrtf(1.f + b1 * b1);
        float t0 = sh[0], t1 = sh[1];
        float q0 = sh[DIMC - 2], q1 = sh[DIMC - 1];
        sh[0]        = C0 * t0 - b0 * q0;
        sh[DIMC - 2] = C0 * q0 - b0 * t0;
        sh[1]        = C1 * t1 - b1 * q1;
        sh[DIMC - 1] = C1 * q1 - b1 * t1;
    }
    __syncthreads();

    // givens_reflection with rot_left (each thread owns its pair: no hazard)
    {
        float w0 = sh[2 * tid], w1 = sh[2 * tid + 1];
        float l0 = rot_left[(size_t)r * DIMC + 2 * tid];
        float l1 = rot_left[(size_t)r * DIMC + 2 * tid + 1];
        float n  = fmaxf(sqrtf(l0 * l0 + l1 * l1), 1e-15f);
        float cl = l0 / n, sl = l1 / n;
        sh[2 * tid]     = cl * w0 + sl * w1;
        sh[2 * tid + 1] = sl * w0 - cl * w1;
    }
    __syncthreads();

    // each lane keeps its 16 head dims in registers
    const float4 H0 = *(const float4*)&sh[lane * 16 + 0];
    const float4 H1 = *(const float4*)&sh[lane * 16 + 4];
    const float4 H2 = *(const float4*)&sh[lane * 16 + 8];
    const float4 H3 = *(const float4*)&sh[lane * 16 + 12];

    // ------- tail loop: 16 tails per warp, 2-deep pipeline, NOT unrolled -------
    #pragma unroll 1
    for (int t = 0; t < TAILS_PER_WARP; ++t) {
        // prefetch next tail's row while reducing the current one
        float4 B0, B1, B2, B3;
        if (t + 1 < TAILS_PER_WARP) {
            int vin = v_idx[b * KC + kbase + t + 1];
            const float4* np = (const float4*)(emb + (size_t)vin * DIMC) + lane * 4;
            B0 = np[0]; B1 = np[1]; B2 = np[2]; B3 = np[3];
        }

        float sq = A0.x*A0.x + A0.y*A0.y + A0.z*A0.z + A0.w*A0.w
                 + A1.x*A1.x + A1.y*A1.y + A1.z*A1.z + A1.w*A1.w
                 + A2.x*A2.x + A2.y*A2.y + A2.z*A2.z + A2.w*A2.w
                 + A3.x*A3.x + A3.y*A3.y + A3.z*A3.z + A3.w*A3.w;
        float dt = H0.x*A0.x + H0.y*A0.y + H0.z*A0.z + H0.w*A0.w
                 + H1.x*A1.x + H1.y*A1.y + H1.z*A1.z + H1.w*A1.w
                 + H2.x*A2.x + H2.y*A2.y + H2.z*A2.z + H2.w*A2.w
                 + H3.x*A3.x + H3.y*A3.y + H3.z*A3.z + H3.w*A3.w;
        float t1raw = A0.y;   // tail element 1 (raw), valid on lane 0
        if (lane == 0) {
            // a_tail = -u1^2 + sum_{j>=2} u_j^2 ; dot only over spatial dims
            sq -= A0.x * A0.x + 2.f * A0.y * A0.y;
            dt -= H0.x * A0.x + H0.y * A0.y;
        }
        #pragma unroll
        for (int o = 16; o; o >>= 1) {
            sq += __shfl_xor_sync(0xffffffffu, sq, o);
            dt += __shfl_xor_sync(0xffffffffu, dt, o);
        }
        if (lane == 0) {
            s_sq[kbase + t] = sq;
            s_dt[kbase + t] = dt;
            s_t1[kbase + t] = t1raw;
        }

        A0 = B0; A1 = B1; A2 = B2; A3 = B3;
    }
    __syncthreads();

    // ------------- parallel epilogue: threads 0..127 each handle one tail -------------
    if (tid < KC) {
        const float h0 = sh[0];
        const float h1 = sh[1];
        const float nh = sqrtf(h0 * h0 + h1 * h1);

        float sq    = s_sq[tid];
        float dtv   = s_dt[tid];
        float t1raw = s_t1[tid];

        float ct, stf;
        if (sq > 0.f) {
            float sp = sqrtf(fmaxf(sq, EPSF));
            ct = coshf(sp);  stf = sinhf(sp) / sp;
        } else {
            float st = sqrtf(fmaxf(-sq, EPSF));
            ct = cosf(st);   stf = sinf(st) / st;
        }
        float ty0 = ct;              // tail time comp 0 (u0=0 -> c)
        float ty1 = stf * t1raw;     // tail time comp 1
        float nt  = sqrtf(ty0 * ty0 + ty1 * ty1);
        float dxy = stf * dtv;       // dot(xs, ys) = s_t * sum h_j u_j

        float cosang = (h0 * ty0 + h1 * ty1) / (nh * nt);
        cosang = fminf(fmaxf(cosang, -1.f + EPSF), 1.f - EPSF);
        float theta = acosf(cosang);

        float inner = nh * nt - dxy;
        float dh = acoshf(fmaxf(inner, 1.f + EPSF));

        float d1 = nh * theta + dh;
        float d2 = nt * theta + dh;
        float dist = fminf(d1 * d1, d2 * d2);

        int vtail = v_idx[b * KC + tid];
        out[b * KC + tid] = MARGINF - dist + bias_head[u] + bias_tail[vtail];
    }
}

extern "C" void kernel_launch(void* const* d_in, const int* in_sizes, int n_in,
                              void* d_out, int out_size)
{
    const float* emb       = (const float*)d_in[0];
    const float* rel_boost = (const float*)d_in[1];
    const float* rot_left  = (const float*)d_in[2];
    const float* rot_right = (const float*)d_in[3];
    const float* bias_head = (const float*)d_in[4];
    const float* bias_tail = (const float*)d_in[5];
    const int*   u_idx     = (const int*)d_in[6];
    const int*   r_idx     = (const int*)d_in[7];
    const int*   v_idx     = (const int*)d_in[8];

    ultrae_kernel<<<BC, TPB>>>(emb, rel_boost, rot_left, rot_right,
                               bias_head, bias_tail, u_idx, r_idx, v_idx,
                               (float*)d_out);
}

// round 5
// speedup vs baseline: 1.8356x; 1.3861x over previous
#include <cuda_runtime.h>
#include <cstdint>

#define DIMC   512
#define BC     512
#define KC     128
#define NWARP  8
#define TPB    256
#define TAILS_PER_WARP (KC / NWARP)   // 16
#define DEPTH  2
#define EPSF   1e-6f
#define MARGINF 2.0f

__device__ __forceinline__ float softplusf(float x) {
    return (x > 20.f) ? x : log1pf(expf(x));
}

__device__ __forceinline__ void cp16(uint32_t dst, const void* src) {
    asm volatile("cp.async.cg.shared.global [%0], [%1], 16;" :: "r"(dst), "l"(src));
}
__device__ __forceinline__ void cp_commit() {
    asm volatile("cp.async.commit_group;");
}
template<int N>
__device__ __forceinline__ void cp_wait() {
    asm volatile("cp.async.wait_group %0;" :: "n"(N));
}

__global__ __launch_bounds__(TPB)
void ultrae_kernel(const float* __restrict__ emb,
                   const float* __restrict__ rel_boost,
                   const float* __restrict__ rot_left,
                   const float* __restrict__ rot_right,
                   const float* __restrict__ bias_head,
                   const float* __restrict__ bias_tail,
                   const int*   __restrict__ u_idx,
                   const int*   __restrict__ r_idx,
                   const int*   __restrict__ v_idx,
                   float*       __restrict__ out)
{
    __shared__ __align__(16) float tbuf[NWARP][DEPTH][DIMC];   // 32 KB gather buffers
    __shared__ __align__(16) float sh[DIMC];
    __shared__ float red[NWARP];
    __shared__ float a_sh;
    __shared__ float s_sq[KC];
    __shared__ float s_dt[KC];
    __shared__ float s_t1[KC];

    const int b    = blockIdx.x;
    const int tid  = threadIdx.x;
    const int lane = tid & 31;
    const int warp = tid >> 5;
    const int u    = u_idx[b];
    const int r    = r_idx[b];

    const int kbase = warp * TAILS_PER_WARP;
    const uint32_t buf0 = (uint32_t)__cvta_generic_to_shared(&tbuf[warp][0][0]);
    const uint32_t buf1 = (uint32_t)__cvta_generic_to_shared(&tbuf[warp][1][0]);

    // ---- issue first two tails' gathers immediately (independent of head math) ----
    {
        int v0 = v_idx[b * KC + kbase + 0];
        const float* src0 = emb + (size_t)v0 * DIMC;
        #pragma unroll
        for (int j = 0; j < 4; ++j)
            cp16(buf0 + (uint32_t)(j * 512 + lane * 16), src0 + j * 128 + lane * 4);
        cp_commit();
        int v1 = v_idx[b * KC + kbase + 1];
        const float* src1 = emb + (size_t)v1 * DIMC;
        #pragma unroll
        for (int j = 0; j < 4; ++j)
            cp16(buf1 + (uint32_t)(j * 512 + lane * 16), src1 + j * 128 + lane * 4);
        cp_commit();
    }

    // ---------------- head preprocessing (per block) ----------------
    const float* hrow = emb + (size_t)u * DIMC;
    float x0 = hrow[2 * tid];
    float x1 = hrow[2 * tid + 1];
    if (tid == 0) x0 = 0.f;                               // proj_tan0
    float acc = (tid == 0) ? (-x1 * x1) : (x0 * x0 + x1 * x1);
    #pragma unroll
    for (int o = 16; o; o >>= 1) acc += __shfl_xor_sync(0xffffffffu, acc, o);
    if (lane == 0) red[warp] = acc;
    __syncthreads();
    if (tid == 0) {
        float a = 0.f;
        #pragma unroll
        for (int w = 0; w < NWARP; ++w) a += red[w];
        a_sh = a;
    }
    __syncthreads();
    const float a = a_sh;

    float c, s;
    if (a > 0.f) {
        float sp = sqrtf(fmaxf(a, EPSF));
        c = coshf(sp);  s = sinhf(sp) / sp;
    } else {
        float st = sqrtf(fmaxf(-a, EPSF));
        c = cosf(st);   s = sinf(st) / st;
    }
    float y0 = (tid == 0) ? c : s * x0;
    float y1 = s * x1;

    // givens_rotations with rot_right
    {
        float g0 = rot_right[(size_t)r * DIMC + 2 * tid];
        float g1 = rot_right[(size_t)r * DIMC + 2 * tid + 1];
        float n  = fmaxf(sqrtf(g0 * g0 + g1 * g1), 1e-15f);
        float cr = g0 / n, sr = g1 / n;
        sh[2 * tid]     = cr * y0 - sr * y1;
        sh[2 * tid + 1] = cr * y1 + sr * y0;
    }
    __syncthreads();

    // Lorentz boost: identity except entries mixing (0,510) and (1,511)
    if (tid == 0) {
        float b0 = softplusf(rel_boost[2 * r]);
        float b1 = softplusf(rel_boost[2 * r + 1]);
        float C0 = sqrtf(1.f + b0 * b0);
        float C1 = sqrtf(1.f + b1 * b1);
        float t0 = sh[0], t1 = sh[1];
        float q0 = sh[DIMC - 2], q1 = sh[DIMC - 1];
        sh[0]        = C0 * t0 - b0 * q0;
        sh[DIMC - 2] = C0 * q0 - b0 * t0;
        sh[1]        = C1 * t1 - b1 * q1;
        sh[DIMC - 1] = C1 * q1 - b1 * t1;
    }
    __syncthreads();

    // givens_reflection with rot_left (each thread owns its pair: no hazard)
    {
        float w0 = sh[2 * tid], w1 = sh[2 * tid + 1];
        float l0 = rot_left[(size_t)r * DIMC + 2 * tid];
        float l1 = rot_left[(size_t)r * DIMC + 2 * tid + 1];
        float n  = fmaxf(sqrtf(l0 * l0 + l1 * l1), 1e-15f);
        float cl = l0 / n, sl = l1 / n;
        sh[2 * tid]     = cl * w0 + sl * w1;
        sh[2 * tid + 1] = sl * w0 - cl * w1;
    }
    __syncthreads();

    // head tile in registers: lane owns float4s at {j*32 + lane}, matching tbuf layout
    float4 H0, H1, H2, H3;
    {
        const float4* hp = (const float4*)sh;
        H0 = hp[0 * 32 + lane];
        H1 = hp[1 * 32 + lane];
        H2 = hp[2 * 32 + lane];
        H3 = hp[3 * 32 + lane];
    }

    // ------- tail loop: 16 tails/warp, cp.async double-buffered, distance 2 -------
    #pragma unroll 1
    for (int t = 0; t < TAILS_PER_WARP; ++t) {
        cp_wait<1>();   // group for tail t complete (1 pending: tail t+1)

        const float4* sp = (const float4*)((t & 1) ? &tbuf[warp][1][0] : &tbuf[warp][0][0]);
        float4 T0 = sp[0 * 32 + lane];
        float4 T1 = sp[1 * 32 + lane];
        float4 T2 = sp[2 * 32 + lane];
        float4 T3 = sp[3 * 32 + lane];

        // prefetch tail t+2 into the buffer just consumed
        if (t + 2 < TAILS_PER_WARP) {
            int vin = v_idx[b * KC + kbase + t + 2];
            const float* src = emb + (size_t)vin * DIMC;
            uint32_t dst = (t & 1) ? buf1 : buf0;
            #pragma unroll
            for (int j = 0; j < 4; ++j)
                cp16(dst + (uint32_t)(j * 512 + lane * 16), src + j * 128 + lane * 4);
        }
        cp_commit();    // always commit (possibly empty) to keep group accounting

        float sq = T0.x*T0.x + T0.y*T0.y + T0.z*T0.z + T0.w*T0.w
                 + T1.x*T1.x + T1.y*T1.y + T1.z*T1.z + T1.w*T1.w
                 + T2.x*T2.x + T2.y*T2.y + T2.z*T2.z + T2.w*T2.w
                 + T3.x*T3.x + T3.y*T3.y + T3.z*T3.z + T3.w*T3.w;
        float dt = H0.x*T0.x + H0.y*T0.y + H0.z*T0.z + H0.w*T0.w
                 + H1.x*T1.x + H1.y*T1.y + H1.z*T1.z + H1.w*T1.w
                 + H2.x*T2.x + H2.y*T2.y + H2.z*T2.z + H2.w*T2.w
                 + H3.x*T3.x + H3.y*T3.y + H3.z*T3.z + H3.w*T3.w;
        float t1raw = T0.y;   // tail element 1 (raw), valid on lane 0
        if (lane == 0) {
            // a_tail = -u1^2 + sum_{j>=2} u_j^2 ; dot only over spatial dims
            sq -= T0.x * T0.x + 2.f * T0.y * T0.y;
            dt -= H0.x * T0.x + H0.y * T0.y;
        }
        #pragma unroll
        for (int o = 16; o; o >>= 1) {
            sq += __shfl_xor_sync(0xffffffffu, sq, o);
            dt += __shfl_xor_sync(0xffffffffu, dt, o);
        }
        if (lane == 0) {
            s_sq[kbase + t] = sq;
            s_dt[kbase + t] = dt;
            s_t1[kbase + t] = t1raw;
        }
    }
    __syncthreads();

    // ------------- parallel epilogue: threads 0..127 each handle one tail -------------
    if (tid < KC) {
        const float h0 = sh[0];
        const float h1 = sh[1];
        const float nh = sqrtf(h0 * h0 + h1 * h1);

        float sq    = s_sq[tid];
        float dtv   = s_dt[tid];
        float t1raw = s_t1[tid];

        float ct, stf;
        if (sq > 0.f) {
            float sp = sqrtf(fmaxf(sq, EPSF));
            ct = coshf(sp);  stf = sinhf(sp) / sp;
        } else {
            float st = sqrtf(fmaxf(-sq, EPSF));
            ct = cosf(st);   stf = sinf(st) / st;
        }
        float ty0 = ct;              // tail time comp 0 (u0=0 -> c)
        float ty1 = stf * t1raw;     // tail time comp 1
        float nt  = sqrtf(ty0 * ty0 + ty1 * ty1);
        float dxy = stf * dtv;       // dot(xs, ys) = s_t * sum h_j u_j

        float cosang = (h0 * ty0 + h1 * ty1) / (nh * nt);
        cosang = fminf(fmaxf(cosang, -1.f + EPSF), 1.f - EPSF);
        float theta = acosf(cosang);

        float inner = nh * nt - dxy;
        float dh = acoshf(fmaxf(inner, 1.f + EPSF));

        float d1 = nh * theta + dh;
        float d2 = nt * theta + dh;
        float dist = fminf(d1 * d1, d2 * d2);

        int vtail = v_idx[b * KC + tid];
        out[b * KC + tid] = MARGINF - dist + bias_head[u] + bias_tail[vtail];
    }
}

extern "C" void kernel_launch(void* const* d_in, const int* in_sizes, int n_in,
                              void* d_out, int out_size)
{
    const float* emb       = (const float*)d_in[0];
    const float* rel_boost = (const float*)d_in[1];
    const float* rot_left  = (const float*)d_in[2];
    const float* rot_right = (const float*)d_in[3];
    const float* bias_head = (const float*)d_in[4];
    const float* bias_tail = (const float*)d_in[5];
    const int*   u_idx     = (const int*)d_in[6];
    const int*   r_idx     = (const int*)d_in[7];
    const int*   v_idx     = (const int*)d_in[8];

    ultrae_kernel<<<BC, TPB>>>(emb, rel_boost, rot_left, rot_right,
                               bias_head, bias_tail, u_idx, r_idx, v_idx,
                               (float*)d_out);
}

// round 6
// speedup vs baseline: 1.8552x; 1.0107x over previous
#include <cuda_runtime.h>
#include <cstdint>

#define DIMC   512
#define BC     512
#define KC     128
#define NWARP  8
#define TPB    256
#define TAILS_PER_WARP (KC / NWARP)   // 16
#define DEPTH  3
#define EPSF   1e-6f
#define MARGINF 2.0f

__device__ __forceinline__ float softplusf(float x) {
    return (x > 20.f) ? x : log1pf(expf(x));
}

__device__ __forceinline__ void cp16(uint32_t dst, const void* src) {
    asm volatile("cp.async.cg.shared.global [%0], [%1], 16;" :: "r"(dst), "l"(src));
}
__device__ __forceinline__ void cp_commit() {
    asm volatile("cp.async.commit_group;");
}
template<int N>
__device__ __forceinline__ void cp_wait() {
    asm volatile("cp.async.wait_group %0;" :: "n"(N));
}

__global__ __launch_bounds__(TPB)
void ultrae_kernel(const float* __restrict__ emb,
                   const float* __restrict__ rel_boost,
                   const float* __restrict__ rot_left,
                   const float* __restrict__ rot_right,
                   const float* __restrict__ bias_head,
                   const float* __restrict__ bias_tail,
                   const int*   __restrict__ u_idx,
                   const int*   __restrict__ r_idx,
                   const int*   __restrict__ v_idx,
                   float*       __restrict__ out)
{
    __shared__ __align__(16) float tbuf[NWARP][DEPTH][DIMC];   // 48 KB gather buffers
    __shared__ __align__(16) float sh[DIMC];
    __shared__ float red[NWARP];
    __shared__ float a_sh;
    __shared__ float s_sq[KC];
    __shared__ float s_dt[KC];
    __shared__ float s_t1[KC];

    const int b    = blockIdx.x;
    const int tid  = threadIdx.x;
    const int lane = tid & 31;
    const int warp = tid >> 5;
    const int u    = u_idx[b];
    const int r    = r_idx[b];

    const int kbase = warp * TAILS_PER_WARP;
    uint32_t bufs[DEPTH];
    #pragma unroll
    for (int d = 0; d < DEPTH; ++d)
        bufs[d] = (uint32_t)__cvta_generic_to_shared(&tbuf[warp][d][0]);

    // ---- issue first DEPTH tails' gathers immediately (independent of head math) ----
    #pragma unroll
    for (int d = 0; d < DEPTH; ++d) {
        int v0 = v_idx[b * KC + kbase + d];
        const float* src = emb + (size_t)v0 * DIMC;
        #pragma unroll
        for (int j = 0; j < 4; ++j)
            cp16(bufs[d] + (uint32_t)(j * 512 + lane * 16), src + j * 128 + lane * 4);
        cp_commit();
    }

    // ---------------- head preprocessing (per block) ----------------
    const float* hrow = emb + (size_t)u * DIMC;
    float x0 = hrow[2 * tid];
    float x1 = hrow[2 * tid + 1];
    if (tid == 0) x0 = 0.f;                               // proj_tan0
    float acc = (tid == 0) ? (-x1 * x1) : (x0 * x0 + x1 * x1);
    #pragma unroll
    for (int o = 16; o; o >>= 1) acc += __shfl_xor_sync(0xffffffffu, acc, o);
    if (lane == 0) red[warp] = acc;
    __syncthreads();
    if (tid == 0) {
        float a = 0.f;
        #pragma unroll
        for (int w = 0; w < NWARP; ++w) a += red[w];
        a_sh = a;
    }
    __syncthreads();
    const float a = a_sh;

    float c, s;
    if (a > 0.f) {
        float sp = sqrtf(fmaxf(a, EPSF));
        c = coshf(sp);  s = sinhf(sp) / sp;
    } else {
        float st = sqrtf(fmaxf(-a, EPSF));
        c = cosf(st);   s = sinf(st) / st;
    }
    float y0 = (tid == 0) ? c : s * x0;
    float y1 = s * x1;

    // givens_rotations with rot_right
    {
        float g0 = rot_right[(size_t)r * DIMC + 2 * tid];
        float g1 = rot_right[(size_t)r * DIMC + 2 * tid + 1];
        float n  = fmaxf(sqrtf(g0 * g0 + g1 * g1), 1e-15f);
        float cr = g0 / n, sr = g1 / n;
        sh[2 * tid]     = cr * y0 - sr * y1;
        sh[2 * tid + 1] = cr * y1 + sr * y0;
    }
    __syncthreads();

    // Lorentz boost: identity except entries mixing (0,510) and (1,511)
    if (tid == 0) {
        float b0 = softplusf(rel_boost[2 * r]);
        float b1 = softplusf(rel_boost[2 * r + 1]);
        float C0 = sqrtf(1.f + b0 * b0);
        float C1 = sqrtf(1.f + b1 * b1);
        float t0 = sh[0], t1 = sh[1];
        float q0 = sh[DIMC - 2], q1 = sh[DIMC - 1];
        sh[0]        = C0 * t0 - b0 * q0;
        sh[DIMC - 2] = C0 * q0 - b0 * t0;
        sh[1]        = C1 * t1 - b1 * q1;
        sh[DIMC - 1] = C1 * q1 - b1 * t1;
    }
    __syncthreads();

    // givens_reflection with rot_left (each thread owns its pair: no hazard)
    {
        float w0 = sh[2 * tid], w1 = sh[2 * tid + 1];
        float l0 = rot_left[(size_t)r * DIMC + 2 * tid];
        float l1 = rot_left[(size_t)r * DIMC + 2 * tid + 1];
        float n  = fmaxf(sqrtf(l0 * l0 + l1 * l1), 1e-15f);
        float cl = l0 / n, sl = l1 / n;
        sh[2 * tid]     = cl * w0 + sl * w1;
        sh[2 * tid + 1] = sl * w0 - cl * w1;
    }
    __syncthreads();

    // head tile in registers: lane owns float4s at {j*32 + lane}, matching tbuf layout
    float4 H0, H1, H2, H3;
    {
        const float4* hp = (const float4*)sh;
        H0 = hp[0 * 32 + lane];
        H1 = hp[1 * 32 + lane];
        H2 = hp[2 * 32 + lane];
        H3 = hp[3 * 32 + lane];
    }

    // ------- tail loop: 16 tails/warp, cp.async triple-buffered, distance 3 -------
    int slot = 0;
    #pragma unroll 1
    for (int t = 0; t < TAILS_PER_WARP; ++t) {
        cp_wait<DEPTH - 1>();   // group for tail t complete (DEPTH-1 pending)

        const float4* sp = (const float4*)&tbuf[warp][slot][0];
        float4 T0 = sp[0 * 32 + lane];
        float4 T1 = sp[1 * 32 + lane];
        float4 T2 = sp[2 * 32 + lane];
        float4 T3 = sp[3 * 32 + lane];

        // prefetch tail t+DEPTH into the buffer just consumed
        if (t + DEPTH < TAILS_PER_WARP) {
            int vin = v_idx[b * KC + kbase + t + DEPTH];
            const float* src = emb + (size_t)vin * DIMC;
            uint32_t dst = bufs[slot];
            #pragma unroll
            for (int j = 0; j < 4; ++j)
                cp16(dst + (uint32_t)(j * 512 + lane * 16), src + j * 128 + lane * 4);
        }
        cp_commit();    // always commit (possibly empty) to keep group accounting

        slot = (slot + 1 == DEPTH) ? 0 : slot + 1;

        float sq = T0.x*T0.x + T0.y*T0.y + T0.z*T0.z + T0.w*T0.w
                 + T1.x*T1.x + T1.y*T1.y + T1.z*T1.z + T1.w*T1.w
                 + T2.x*T2.x + T2.y*T2.y + T2.z*T2.z + T2.w*T2.w
                 + T3.x*T3.x + T3.y*T3.y + T3.z*T3.z + T3.w*T3.w;
        float dt = H0.x*T0.x + H0.y*T0.y + H0.z*T0.z + H0.w*T0.w
                 + H1.x*T1.x + H1.y*T1.y + H1.z*T1.z + H1.w*T1.w
                 + H2.x*T2.x + H2.y*T2.y + H2.z*T2.z + H2.w*T2.w
                 + H3.x*T3.x + H3.y*T3.y + H3.z*T3.z + H3.w*T3.w;
        float t1raw = T0.y;   // tail element 1 (raw), valid on lane 0
        if (lane == 0) {
            // a_tail = -u1^2 + sum_{j>=2} u_j^2 ; dot only over spatial dims
            sq -= T0.x * T0.x + 2.f * T0.y * T0.y;
            dt -= H0.x * T0.x + H0.y * T0.y;
        }
        #pragma unroll
        for (int o = 16; o; o >>= 1) {
            sq += __shfl_xor_sync(0xffffffffu, sq, o);
            dt += __shfl_xor_sync(0xffffffffu, dt, o);
        }
        if (lane == 0) {
            s_sq[kbase + t] = sq;
            s_dt[kbase + t] = dt;
            s_t1[kbase + t] = t1raw;
        }
    }
    __syncthreads();

    // ------------- parallel epilogue: threads 0..127 each handle one tail -------------
    if (tid < KC) {
        const float h0 = sh[0];
        const float h1 = sh[1];
        const float nh = sqrtf(h0 * h0 + h1 * h1);

        float sq    = s_sq[tid];
        float dtv   = s_dt[tid];
        float t1raw = s_t1[tid];

        float ct, stf;
        if (sq > 0.f) {
            float sp = sqrtf(fmaxf(sq, EPSF));
            ct = coshf(sp);  stf = sinhf(sp) / sp;
        } else {
            float st = sqrtf(fmaxf(-sq, EPSF));
            ct = cosf(st);   stf = sinf(st) / st;
        }
        float ty0 = ct;              // tail time comp 0 (u0=0 -> c)
        float ty1 = stf * t1raw;     // tail time comp 1
        float nt  = sqrtf(ty0 * ty0 + ty1 * ty1);
        float dxy = stf * dtv;       // dot(xs, ys) = s_t * sum h_j u_j

        float cosang = (h0 * ty0 + h1 * ty1) / (nh * nt);
        cosang = fminf(fmaxf(cosang, -1.f + EPSF), 1.f - EPSF);
        float theta = acosf(cosang);

        float inner = nh * nt - dxy;
        float dh = acoshf(fmaxf(inner, 1.f + EPSF));

        float d1 = nh * theta + dh;
        float d2 = nt * theta + dh;
        float dist = fminf(d1 * d1, d2 * d2);

        int vtail = v_idx[b * KC + tid];
        out[b * KC + tid] = MARGINF - dist + bias_head[u] + bias_tail[vtail];
    }
}

extern "C" void kernel_launch(void* const* d_in, const int* in_sizes, int n_in,
                              void* d_out, int out_size)
{
    const float* emb       = (const float*)d_in[0];
    const float* rel_boost = (const float*)d_in[1];
    const float* rot_left  = (const float*)d_in[2];
    const float* rot_right = (const float*)d_in[3];
    const float* bias_head = (const float*)d_in[4];
    const float* bias_tail = (const float*)d_in[5];
    const int*   u_idx     = (const int*)d_in[6];
    const int*   r_idx     = (const int*)d_in[7];
    const int*   v_idx     = (const int*)d_in[8];

    ultrae_kernel<<<BC, TPB>>>(emb, rel_boost, rot_left, rot_right,
                               bias_head, bias_tail, u_idx, r_idx, v_idx,
                               (float*)d_out);
}